// round 9
// baseline (speedup 1.0000x reference)
#include <cuda_runtime.h>
#include <cuda_fp16.h>
#include <cstdint>

#define BATCH  1024
#define TSTEPS 80
#define EDIM   100
#define UDIM   256
#define VOCAB  10000
#define NCOL   1024   // 4 gates * U, packed col = u*4+g (g:0=f,1=i,2=c,3=o)
#define NBLK   128

// ---- smem layout (bytes) ----
#define A_PITCH 80
#define A_WBUF  2560           // 32 rows * 80  (one chunk, one warp)
#define A_WARP  7680           // 3 buffers per warp
#define SM_A    0              // 8 warps * 7680 = 61440
#define SM_W1   61440          // 64 n * 528   = 33792
#define SM_W2   95232          // 64 n * 1040  = 66560
#define SMEM_TOTAL 161792

// packed weight slice per nT (fp16 elems)
#define WSLICE   50176         // 64*264 + 64*520
#define W2BASE_E 16896

// ---------------- device scratch ----------------
__device__ float    g_proj[(size_t)VOCAB * NCOL];  // emb@Wx+b1, fp32, gate-interleaved
__device__ __half   g_Wpk[16 * WSLICE];            // packed fp16 weights per nT
__device__ float    g_b2p[NCOL];
__device__ __half   g_hbf[2][BATCH][512];          // [buf][b][col] 0-255 h2, 256-511 h1
__device__ float    g_h2f[BATCH][UDIM];
__device__ unsigned g_cntg[8 * 32];                // per-mT-group barrier counters (padded)

// ---------------- helpers ----------------
__device__ __forceinline__ uint32_t smem_u32(const void *p) {
    uint32_t a;
    asm("{ .reg .u64 t; cvta.to.shared.u64 t, %1; cvt.u32.u64 %0, t; }" : "=r"(a) : "l"(p));
    return a;
}
__device__ __forceinline__ void mma_f16(float *c, const uint32_t *a, const uint32_t *b) {
    asm volatile(
        "mma.sync.aligned.m16n8k16.row.col.f32.f16.f16.f32 "
        "{%0,%1,%2,%3}, {%4,%5,%6,%7}, {%8,%9}, {%0,%1,%2,%3};"
        : "+f"(c[0]), "+f"(c[1]), "+f"(c[2]), "+f"(c[3])
        : "r"(a[0]), "r"(a[1]), "r"(a[2]), "r"(a[3]), "r"(b[0]), "r"(b[1]));
}
__device__ __forceinline__ void ldmatrix4(uint32_t *r, uint32_t addr) {
    asm volatile("ldmatrix.sync.aligned.m8n8.x4.shared.b16 {%0,%1,%2,%3}, [%4];"
                 : "=r"(r[0]), "=r"(r[1]), "=r"(r[2]), "=r"(r[3]) : "r"(addr));
}
__device__ __forceinline__ void cpa16(uint32_t dst, const void *src) {
    asm volatile("cp.async.cg.shared.global [%0], [%1], 16;" :: "r"(dst), "l"(src) : "memory");
}
// stage one 32-half row segment (64 B) per thread: one chunk per warp
__device__ __forceinline__ void stage4(uint32_t dst, const __half *s) {
    cpa16(dst, s);
    cpa16(dst + 16, s + 8);
    cpa16(dst + 32, s + 16);
    cpa16(dst + 48, s + 24);
    asm volatile("cp.async.commit_group;" ::: "memory");
}
__device__ __forceinline__ float tanhap(float x) {
    float y; asm("tanh.approx.f32 %0, %1;" : "=f"(y) : "f"(x)); return y;
}
__device__ __forceinline__ float sigap(float x) {
    return fmaf(tanhap(0.5f * x), 0.5f, 0.5f);
}
// per-mT-group barrier (16 CTAs): release-red + acquire-ld spin
__device__ __forceinline__ void gsync(int grp, unsigned &target) {
    __syncthreads();
    if (threadIdx.x == 0) {
        unsigned *ctr = &g_cntg[grp * 32];
        asm volatile("red.release.gpu.global.add.u32 [%0], %1;" :: "l"(ctr), "r"(1u) : "memory");
        target += 16;
        unsigned v;
        do {
            asm volatile("ld.acquire.gpu.global.u32 %0, [%1];" : "=r"(v) : "l"(ctr) : "memory");
        } while (v < target);
    }
    __syncthreads();
}

// ---------------- init: pack fp16 weights, zero state ----------------
__global__ void init_kernel(
    const float *wf1, const float *wi1, const float *wc1, const float *wo1,
    const float *wf2, const float *wi2, const float *wc2, const float *wo2,
    const float *bf2, const float *bi2, const float *bc2, const float *bo2)
{
    long i = (long)blockIdx.x * blockDim.x + threadIdx.x;
    long stride = (long)gridDim.x * blockDim.x;
    for (long j = i; j < 524288L; j += stride) ((uint32_t *)g_hbf)[j] = 0u;
    for (long j = i; j < 256; j += stride) g_cntg[j] = 0u;
    for (long j = i; j < 16L * 64L * 768L; j += stride) {
        int nT = (int)(j / (64 * 768));
        int rem = (int)(j % (64 * 768));
        int n = rem / 768, k = rem % 768;
        int col = nT * 64 + n;
        int u = col >> 2, g = col & 3;
        if (k < 256) {
            const float *w = (g == 0) ? wf1 : (g == 1) ? wi1 : (g == 2) ? wc1 : wo1;
            g_Wpk[(long)nT * WSLICE + n * 264 + k] = __float2half(w[k * UDIM + u]);
        } else {
            int k2 = k - 256;
            const float *w = (g == 0) ? wf2 : (g == 1) ? wi2 : (g == 2) ? wc2 : wo2;
            g_Wpk[(long)nT * WSLICE + W2BASE_E + n * 520 + k2] = __float2half(w[k2 * UDIM + u]);
        }
    }
    for (long j = i; j < NCOL; j += stride) {
        int g = (int)(j & 3), u = (int)(j >> 2);
        const float *b = (g == 0) ? bf2 : (g == 1) ? bi2 : (g == 2) ? bc2 : bo2;
        g_b2p[j] = b[u];
    }
}

// ---------------- proj (fp32): proj[v][u*4+g] = emb[v,:] @ W{g}1[x-rows] + b{g}1 ----------------
__global__ __launch_bounds__(256) void proj_kernel(
    const float *__restrict__ emb,
    const float *__restrict__ wf1, const float *__restrict__ wi1,
    const float *__restrict__ wc1, const float *__restrict__ wo1,
    const float *__restrict__ bf1, const float *__restrict__ bi1,
    const float *__restrict__ bc1, const float *__restrict__ bo1)
{
    __shared__ float As[16][68];
    __shared__ float Bs[16][128];
    const int tid = threadIdx.x;
    const int tx = tid & 15, ty = tid >> 4;
    const int bid = blockIdx.x;
    const int mT = bid >> 3, nT = bid & 7;
    const int m0 = mT << 6, n0 = nT << 7;
    const int la_m = tid >> 2, la_k = (tid & 3) << 2;
    const int lb_k = tid >> 4, lb_n = (tid & 15) << 3;

    float acc[4][8];
#pragma unroll
    for (int r = 0; r < 4; ++r)
#pragma unroll
        for (int j = 0; j < 8; ++j) acc[r][j] = 0.0f;

#pragma unroll 1
    for (int kt = 0; kt < 7; ++kt) {
        const int k0 = kt << 4;
        float4 pa = make_float4(0.f, 0.f, 0.f, 0.f);
        {
            int v = m0 + la_m, k = k0 + la_k;
            if (v < VOCAB && k < EDIM)
                pa = *(const float4 *)(emb + (size_t)v * EDIM + k);
        }
        float pb[8];
        {
            int k = k0 + lb_k;
            bool val = (k < EDIM);
            int wrow = (UDIM + k) * UDIM;
            int uc = (n0 + lb_n) >> 2;
            pb[0] = val ? __ldg(&wf1[wrow + uc]) : 0.f;
            pb[1] = val ? __ldg(&wi1[wrow + uc]) : 0.f;
            pb[2] = val ? __ldg(&wc1[wrow + uc]) : 0.f;
            pb[3] = val ? __ldg(&wo1[wrow + uc]) : 0.f;
            pb[4] = val ? __ldg(&wf1[wrow + uc + 1]) : 0.f;
            pb[5] = val ? __ldg(&wi1[wrow + uc + 1]) : 0.f;
            pb[6] = val ? __ldg(&wc1[wrow + uc + 1]) : 0.f;
            pb[7] = val ? __ldg(&wo1[wrow + uc + 1]) : 0.f;
        }
        __syncthreads();
        As[la_k + 0][la_m] = pa.x;
        As[la_k + 1][la_m] = pa.y;
        As[la_k + 2][la_m] = pa.z;
        As[la_k + 3][la_m] = pa.w;
#pragma unroll
        for (int j = 0; j < 8; ++j) Bs[lb_k][lb_n + j] = pb[j];
        __syncthreads();
#pragma unroll
        for (int kk = 0; kk < 16; ++kk) {
            float4 a4 = *(const float4 *)&As[kk][ty << 2];
            float4 b4a = *(const float4 *)&Bs[kk][tx << 3];
            float4 b4b = *(const float4 *)&Bs[kk][(tx << 3) + 4];
            float av[4] = {a4.x, a4.y, a4.z, a4.w};
            float bv[8] = {b4a.x, b4a.y, b4a.z, b4a.w, b4b.x, b4b.y, b4b.z, b4b.w};
#pragma unroll
            for (int r = 0; r < 4; ++r)
#pragma unroll
                for (int j = 0; j < 8; ++j) acc[r][j] = fmaf(av[r], bv[j], acc[r][j]);
        }
    }
#pragma unroll
    for (int r = 0; r < 4; ++r) {
        int v = m0 + (ty << 2) + r;
        if (v < VOCAB) {
            int colb = n0 + (tx << 3);
            int u = colb >> 2;
            float *dst = g_proj + (size_t)v * NCOL + colb;
            dst[0] = acc[r][0] + __ldg(&bf1[u]);
            dst[1] = acc[r][1] + __ldg(&bi1[u]);
            dst[2] = acc[r][2] + __ldg(&bc1[u]);
            dst[3] = acc[r][3] + __ldg(&bo1[u]);
            dst[4] = acc[r][4] + __ldg(&bf1[u + 1]);
            dst[5] = acc[r][5] + __ldg(&bi1[u + 1]);
            dst[6] = acc[r][6] + __ldg(&bc1[u + 1]);
            dst[7] = acc[r][7] + __ldg(&bo1[u + 1]);
        }
    }
}

// chunk source: per-thread row pointer + column base for chunk c (c in 0..25)
__device__ __forceinline__ const __half *chunk_src(int c, const __half *hcur_t, const __half *hnxt_t) {
    if (c < 8)  return hcur_t + 256 + c * 32;      // phase A: h1_old
    if (c < 16) return hcur_t + (c - 8) * 32;      // phase B half1: h2_old
    return hnxt_t + 256 + ((c - 16) & 7) * 32;     // phase B half2 / next-step A: h1_new
}

// 16 MMAs on one BK=32 chunk; A + B fragments via ldmatrix
__device__ __forceinline__ void chunk_body(
    const uint32_t (&a_base)[2], uint32_t abuf, const uint32_t (&wbq)[2],
    uint32_t koff, float (&acc)[2][4][4])
{
#pragma unroll
    for (int ks = 0; ks < 2; ++ks) {
        uint32_t a0[4], a1[4];
        ldmatrix4(a0, a_base[0] + abuf + ks * 32);
        ldmatrix4(a1, a_base[1] + abuf + ks * 32);
        uint32_t b0[4], b1[4];
        ldmatrix4(b0, wbq[0] + koff + ks * 32);    // fn0: {b0[0],b0[1]}, fn1: {b0[2],b0[3]}
        ldmatrix4(b1, wbq[1] + koff + ks * 32);    // fn2, fn3
        mma_f16(acc[0][0], a0, b0 + 0);
        mma_f16(acc[1][0], a1, b0 + 0);
        mma_f16(acc[0][1], a0, b0 + 2);
        mma_f16(acc[1][1], a1, b0 + 2);
        mma_f16(acc[0][2], a0, b1 + 0);
        mma_f16(acc[1][2], a1, b1 + 0);
        mma_f16(acc[0][3], a0, b1 + 2);
        mma_f16(acc[1][3], a1, b1 + 2);
    }
}

// epilogue: combine gate quads via shfl, update c-state, write h (fp16)
template <bool PHASEA>
__device__ __forceinline__ void epilogue(
    float (&acc)[2][4][4], float (&cst)[2][4], const float4 (&ad)[2][4],
    const int (&brow)[2], int ug0, int l, int nxt, bool storef)
{
    const int odd = l & 1;
#pragma unroll
    for (int fm = 0; fm < 2; ++fm) {
        int b = brow[fm];
#pragma unroll
        for (int fn = 0; fn < 4; ++fn) {
            float c0 = acc[fm][fn][0], c1 = acc[fm][fn][1];
            float c2 = acc[fm][fn][2], c3 = acc[fm][fn][3];
            float s0 = __shfl_xor_sync(0xffffffffu, c0, 1);
            float s1 = __shfl_xor_sync(0xffffffffu, c1, 1);
            float s2 = __shfl_xor_sync(0xffffffffu, c2, 1);
            float s3 = __shfl_xor_sync(0xffffffffu, c3, 1);
            float gf = odd ? s2 : c0;
            float gi = odd ? s3 : c1;
            float gc = odd ? c2 : s0;
            float go = odd ? c3 : s1;
            float4 a4 = ad[fm][fn];
            float pf = gf + a4.x, pi = gi + a4.y, pc = gc + a4.z, po = go + a4.w;
            float cn = sigap(pf) * cst[fm][fn] + sigap(pi) * tanhap(pc);
            cst[fm][fn] = cn;
            float h = sigap(po) * tanhap(cn);
            int ug = ug0 + fn * 2;
            int col = (PHASEA ? 256 : 0) + ug;
            g_hbf[nxt][b][col] = __float2half(h);
            if (!PHASEA && storef) g_h2f[b][ug] = h;
        }
    }
}

// ---------------- persistent recurrent kernel ----------------
__global__ __launch_bounds__(256, 1) void lstm_kernel(
    const int *__restrict__ tokens,
    const float *__restrict__ w_out,
    const float *__restrict__ b_out,
    float *__restrict__ out)
{
    extern __shared__ char smem[];
    const uint32_t sb = smem_u32(smem);
    const int tid = threadIdx.x;
    const int bid = blockIdx.x;
    const int wid = tid >> 5, l = tid & 31;
    const int mT = bid >> 4, nT = bid & 15;
    const int m0 = mT << 7;
    const int mw = wid & 3, nw = wid >> 2;

    // preload resident fp16 weight slice (100352 B, linear)
    {
        const float4 *src = (const float4 *)(g_Wpk + (size_t)nT * WSLICE);
        float4 *dst = (float4 *)(smem + SM_W1);
        for (int i = tid; i < 6272; i += 256) dst[i] = src[i];
    }

    // warp-private A staging region
    const uint32_t warpA = sb + SM_A + wid * A_WARP;
    // A ldmatrix lane addresses (within one 32-row buffer)
    uint32_t a_base[2];
#pragma unroll
    for (int fm = 0; fm < 2; ++fm)
        a_base[fm] = warpA + (fm * 16 + (l & 15)) * A_PITCH + (l >> 4) * 16;
    // B ldmatrix lane addresses: q covers fn pair {2q, 2q+1}
    uint32_t wb1q[2], wb2q[2];
#pragma unroll
    for (int q = 0; q < 2; ++q) {
        int fn = q * 2 + (l >> 4);
        int n = nw * 32 + fn * 8 + (l & 7);
        uint32_t hi = ((l >> 3) & 1) * 16;
        wb1q[q] = sb + SM_W1 + n * 528 + hi;
        wb2q[q] = sb + SM_W2 + n * 1040 + hi;
    }
    // staging: thread l owns row (mw*32 + l) of the CTA's 128-row stripe
    const int grow = m0 + mw * 32 + l;

    // epilogue row/col constants
    const int odd = l & 1;
    const int ul_b = nw * 8 + ((l & 3) >> 1);
    const int ug0 = nT * 16 + ul_b;
    int brow[2];
#pragma unroll
    for (int fm = 0; fm < 2; ++fm)
        brow[fm] = m0 + mw * 32 + fm * 16 + (l >> 2) + (odd ? 8 : 0);

    // layer-2 bias addends: constant across steps
    float4 adB[2][4];
#pragma unroll
    for (int fn = 0; fn < 4; ++fn) {
        float4 v = *(const float4 *)(g_b2p + 4 * (ug0 + fn * 2));
        adB[0][fn] = v;
        adB[1][fn] = v;
    }

    float c1st[2][4], c2st[2][4];
#pragma unroll
    for (int a = 0; a < 2; ++a)
#pragma unroll
        for (int b = 0; b < 4; ++b) { c1st[a][b] = 0.f; c2st[a][b] = 0.f; }

    unsigned target = 0;
    __syncthreads();   // weights resident

    // prologue: stage chunks 0,1 of t=0 (h1_old)
    {
        const __half *h0_t = &g_hbf[0][grow][0];
        stage4(warpA + 0 * A_WBUF + l * A_PITCH, h0_t + 256);
        stage4(warpA + 1 * A_WBUF + l * A_PITCH, h0_t + 288);
    }

#pragma unroll 1
    for (int t = 0; t < TSTEPS; ++t) {
        const int cur = t & 1, nxt = cur ^ 1;
        const __half *hcur_t = &g_hbf[cur][grow][0];
        const __half *hnxt_t = &g_hbf[nxt][grow][0];
        const bool last = (t == TSTEPS - 1);

        // hoist epilogue-A addends (token-dependent proj gathers)
        float4 adA[2][4];
#pragma unroll
        for (int fm = 0; fm < 2; ++fm) {
            int tok = __ldg(&tokens[brow[fm] * TSTEPS + t]);
            const float4 *p = (const float4 *)(g_proj + (size_t)tok * NCOL) + ug0;
#pragma unroll
            for (int fn = 0; fn < 4; ++fn) adA[fm][fn] = __ldg(p + fn * 2);
        }

        // ---- SEG A: layer-1, chunks 0..7 ----
        float acc1[2][4][4];
#pragma unroll
        for (int a = 0; a < 2; ++a)
#pragma unroll
            for (int f = 0; f < 4; ++f)
#pragma unroll
                for (int j = 0; j < 4; ++j) acc1[a][f][j] = 0.f;
#pragma unroll
        for (int k = 0; k < 8; ++k) {
            asm volatile("cp.async.wait_group 1;" ::: "memory");
            stage4(warpA + ((k + 2) % 3) * A_WBUF + l * A_PITCH, chunk_src(k + 2, hcur_t, hnxt_t));
            chunk_body(a_base, (k % 3) * A_WBUF, wb1q, k * 64, acc1);
        }
        epilogue<true>(acc1, c1st, adA, brow, ug0, l, nxt, false);

        // ---- SEG B1: layer-2 over h2_old, chunks 8..15 ----
        float acc2[2][4][4];
#pragma unroll
        for (int a = 0; a < 2; ++a)
#pragma unroll
            for (int f = 0; f < 4; ++f)
#pragma unroll
                for (int j = 0; j < 4; ++j) acc2[a][f][j] = 0.f;
#pragma unroll
        for (int k = 8; k < 16; ++k) {
            if (k < 15) { asm volatile("cp.async.wait_group 1;" ::: "memory"); }
            else        { asm volatile("cp.async.wait_group 0;" ::: "memory"); }
            if (k + 2 < 16)
                stage4(warpA + ((k + 2) % 3) * A_WBUF + l * A_PITCH, chunk_src(k + 2, hcur_t, hnxt_t));
            chunk_body(a_base, (k % 3) * A_WBUF, wb2q, (k - 8) * 64, acc2);
        }
        gsync(mT, target);

        // ---- SEG B2: layer-2 over h1_new, chunks 16..23 ----
        stage4(warpA + (16 % 3) * A_WBUF + l * A_PITCH, chunk_src(16, hcur_t, hnxt_t));
        stage4(warpA + (17 % 3) * A_WBUF + l * A_PITCH, chunk_src(17, hcur_t, hnxt_t));
#pragma unroll
        for (int k = 16; k < 24; ++k) {
            if (k == 23 && last) { asm volatile("cp.async.wait_group 0;" ::: "memory"); }
            else                 { asm volatile("cp.async.wait_group 1;" ::: "memory"); }
            if (k + 2 < 24 || !last)
                stage4(warpA + ((k + 2) % 3) * A_WBUF + l * A_PITCH, chunk_src(k + 2, hcur_t, hnxt_t));
            chunk_body(a_base, (k % 3) * A_WBUF, wb2q, (k - 8) * 64, acc2);
        }
        epilogue<false>(acc2, c2st, adB, brow, ug0, l, nxt, last);
        gsync(mT, target);
    }

    // ---- output: out[b] = sigmoid(h2[b] . w_out + b_out) ----
    {
        int w = (bid << 3) + wid;
        float s = 0.0f;
#pragma unroll
        for (int k = l; k < UDIM; k += 32)
            s += g_h2f[w][k] * __ldg(&w_out[k]);
#pragma unroll
        for (int off = 16; off > 0; off >>= 1)
            s += __shfl_down_sync(0xffffffffu, s, off);
        if (l == 0) out[w] = sigap(s + __ldg(&b_out[0]));
    }
}

// ---------------- launch ----------------
extern "C" void kernel_launch(void *const *d_in, const int *in_sizes, int n_in,
                              void *d_out, int out_size)
{
    const int   *tokens = (const int *)d_in[0];
    const float *emb = (const float *)d_in[1];
    const float *wf1 = (const float *)d_in[2];
    const float *bf1 = (const float *)d_in[3];
    const float *wi1 = (const float *)d_in[4];
    const float *bi1 = (const float *)d_in[5];
    const float *wc1 = (const float *)d_in[6];
    const float *bc1 = (const float *)d_in[7];
    const float *wo1 = (const float *)d_in[8];
    const float *bo1 = (const float *)d_in[9];
    const float *wf2 = (const float *)d_in[10];
    const float *bf2 = (const float *)d_in[11];
    const float *wi2 = (const float *)d_in[12];
    const float *bi2 = (const float *)d_in[13];
    const float *wc2 = (const float *)d_in[14];
    const float *bc2 = (const float *)d_in[15];
    const float *wo2 = (const float *)d_in[16];
    const float *bo2 = (const float *)d_in[17];
    const float *w_out = (const float *)d_in[18];
    const float *b_out = (const float *)d_in[19];
    float *out = (float *)d_out;

    cudaFuncSetAttribute(lstm_kernel, cudaFuncAttributeMaxDynamicSharedMemorySize, SMEM_TOTAL);

    init_kernel<<<1024, 256>>>(wf1, wi1, wc1, wo1, wf2, wi2, wc2, wo2, bf2, bi2, bc2, bo2);
    proj_kernel<<<1256, 256>>>(emb, wf1, wi1, wc1, wo1, bf1, bi1, bc1, bo1);
    lstm_kernel<<<NBLK, 256, SMEM_TOTAL>>>(tokens, w_out, b_out, out);
}

// round 10
// speedup vs baseline: 1.5734x; 1.5734x over previous
#include <cuda_runtime.h>
#include <cuda_fp16.h>
#include <cstdint>

#define BATCH  1024
#define TSTEPS 80
#define EDIM   100
#define UDIM   256
#define VOCAB  10000
#define NCOL   1024   // 4 gates * U, packed col = u*4+g (g:0=f,1=i,2=c,3=o)
#define NBLK   128

// ---- smem layout (bytes) ----
#define A_PITCH 80
#define A_BUF   10240          // 128 rows * 80
#define SM_A    0              // 3 buffers = 30720
#define SM_W1   30720          // 64 n * 528
#define SM_W2   64512          // 64 n * 1040
#define SMEM_TOTAL 131072

// packed weight slice per nT (fp16 elems)
#define WSLICE   50176         // 64*264 + 64*520
#define W2BASE_E 16896

// ---------------- device scratch ----------------
__device__ float    g_proj[(size_t)VOCAB * NCOL];  // emb@Wx+b1, fp32, gate-interleaved
__device__ __half   g_Wpk[16 * WSLICE];            // packed fp16 weights per nT
__device__ float    g_b2p[NCOL];
__device__ __half   g_hbf[2][BATCH][512];          // [buf][b][col] 0-255 h2, 256-511 h1
__device__ float    g_h2f[BATCH][UDIM];
__device__ unsigned g_cntg[8 * 32];                // per-mT-group barrier counters (padded)

// ---------------- helpers ----------------
__device__ __forceinline__ uint32_t smem_u32(const void *p) {
    uint32_t a;
    asm("{ .reg .u64 t; cvta.to.shared.u64 t, %1; cvt.u32.u64 %0, t; }" : "=r"(a) : "l"(p));
    return a;
}
__device__ __forceinline__ void mma_f16(float *c, const uint32_t *a, const uint32_t *b) {
    asm volatile(
        "mma.sync.aligned.m16n8k16.row.col.f32.f16.f16.f32 "
        "{%0,%1,%2,%3}, {%4,%5,%6,%7}, {%8,%9}, {%0,%1,%2,%3};"
        : "+f"(c[0]), "+f"(c[1]), "+f"(c[2]), "+f"(c[3])
        : "r"(a[0]), "r"(a[1]), "r"(a[2]), "r"(a[3]), "r"(b[0]), "r"(b[1]));
}
__device__ __forceinline__ void ldmatrix4(uint32_t *r, uint32_t addr) {
    asm volatile("ldmatrix.sync.aligned.m8n8.x4.shared.b16 {%0,%1,%2,%3}, [%4];"
                 : "=r"(r[0]), "=r"(r[1]), "=r"(r[2]), "=r"(r[3]) : "r"(addr));
}
__device__ __forceinline__ void cpa16(uint32_t dst, const void *src) {
    asm volatile("cp.async.cg.shared.global [%0], [%1], 16;" :: "r"(dst), "l"(src) : "memory");
}
__device__ __forceinline__ void stage(uint32_t dst, const __half *s) {
    cpa16(dst, s);
    cpa16(dst + 16, s + 8);
    asm volatile("cp.async.commit_group;" ::: "memory");
}
__device__ __forceinline__ float tanhap(float x) {
    float y; asm("tanh.approx.f32 %0, %1;" : "=f"(y) : "f"(x)); return y;
}
__device__ __forceinline__ float sigap(float x) {
    return fmaf(tanhap(0.5f * x), 0.5f, 0.5f);
}
// per-mT-group barrier (16 CTAs): release-red + acquire-ld spin
__device__ __forceinline__ void gsync(int grp, unsigned &target) {
    __syncthreads();
    if (threadIdx.x == 0) {
        unsigned *ctr = &g_cntg[grp * 32];
        asm volatile("red.release.gpu.global.add.u32 [%0], %1;" :: "l"(ctr), "r"(1u) : "memory");
        target += 16;
        unsigned v;
        do {
            asm volatile("ld.acquire.gpu.global.u32 %0, [%1];" : "=r"(v) : "l"(ctr) : "memory");
        } while (v < target);
    }
    __syncthreads();
}

// ---------------- init: pack fp16 weights, zero state ----------------
__global__ void init_kernel(
    const float *wf1, const float *wi1, const float *wc1, const float *wo1,
    const float *wf2, const float *wi2, const float *wc2, const float *wo2,
    const float *bf2, const float *bi2, const float *bc2, const float *bo2)
{
    long i = (long)blockIdx.x * blockDim.x + threadIdx.x;
    long stride = (long)gridDim.x * blockDim.x;
    for (long j = i; j < 524288L; j += stride) ((uint32_t *)g_hbf)[j] = 0u;
    for (long j = i; j < 256; j += stride) g_cntg[j] = 0u;
    for (long j = i; j < 16L * 64L * 768L; j += stride) {
        int nT = (int)(j / (64 * 768));
        int rem = (int)(j % (64 * 768));
        int n = rem / 768, k = rem % 768;
        int col = nT * 64 + n;
        int u = col >> 2, g = col & 3;
        if (k < 256) {
            const float *w = (g == 0) ? wf1 : (g == 1) ? wi1 : (g == 2) ? wc1 : wo1;
            g_Wpk[(long)nT * WSLICE + n * 264 + k] = __float2half(w[k * UDIM + u]);
        } else {
            int k2 = k - 256;
            const float *w = (g == 0) ? wf2 : (g == 1) ? wi2 : (g == 2) ? wc2 : wo2;
            g_Wpk[(long)nT * WSLICE + W2BASE_E + n * 520 + k2] = __float2half(w[k2 * UDIM + u]);
        }
    }
    for (long j = i; j < NCOL; j += stride) {
        int g = (int)(j & 3), u = (int)(j >> 2);
        const float *b = (g == 0) ? bf2 : (g == 1) ? bi2 : (g == 2) ? bc2 : bo2;
        g_b2p[j] = b[u];
    }
}

// ---------------- proj (fp32): proj[v][u*4+g] = emb[v,:] @ W{g}1[x-rows] + b{g}1 ----------------
__global__ __launch_bounds__(256) void proj_kernel(
    const float *__restrict__ emb,
    const float *__restrict__ wf1, const float *__restrict__ wi1,
    const float *__restrict__ wc1, const float *__restrict__ wo1,
    const float *__restrict__ bf1, const float *__restrict__ bi1,
    const float *__restrict__ bc1, const float *__restrict__ bo1)
{
    __shared__ float As[16][68];
    __shared__ float Bs[16][128];
    const int tid = threadIdx.x;
    const int tx = tid & 15, ty = tid >> 4;
    const int bid = blockIdx.x;
    const int mT = bid >> 3, nT = bid & 7;
    const int m0 = mT << 6, n0 = nT << 7;
    const int la_m = tid >> 2, la_k = (tid & 3) << 2;
    const int lb_k = tid >> 4, lb_n = (tid & 15) << 3;

    float acc[4][8];
#pragma unroll
    for (int r = 0; r < 4; ++r)
#pragma unroll
        for (int j = 0; j < 8; ++j) acc[r][j] = 0.0f;

#pragma unroll 1
    for (int kt = 0; kt < 7; ++kt) {
        const int k0 = kt << 4;
        float4 pa = make_float4(0.f, 0.f, 0.f, 0.f);
        {
            int v = m0 + la_m, k = k0 + la_k;
            if (v < VOCAB && k < EDIM)
                pa = *(const float4 *)(emb + (size_t)v * EDIM + k);
        }
        float pb[8];
        {
            int k = k0 + lb_k;
            bool val = (k < EDIM);
            int wrow = (UDIM + k) * UDIM;
            int uc = (n0 + lb_n) >> 2;
            pb[0] = val ? __ldg(&wf1[wrow + uc]) : 0.f;
            pb[1] = val ? __ldg(&wi1[wrow + uc]) : 0.f;
            pb[2] = val ? __ldg(&wc1[wrow + uc]) : 0.f;
            pb[3] = val ? __ldg(&wo1[wrow + uc]) : 0.f;
            pb[4] = val ? __ldg(&wf1[wrow + uc + 1]) : 0.f;
            pb[5] = val ? __ldg(&wi1[wrow + uc + 1]) : 0.f;
            pb[6] = val ? __ldg(&wc1[wrow + uc + 1]) : 0.f;
            pb[7] = val ? __ldg(&wo1[wrow + uc + 1]) : 0.f;
        }
        __syncthreads();
        As[la_k + 0][la_m] = pa.x;
        As[la_k + 1][la_m] = pa.y;
        As[la_k + 2][la_m] = pa.z;
        As[la_k + 3][la_m] = pa.w;
#pragma unroll
        for (int j = 0; j < 8; ++j) Bs[lb_k][lb_n + j] = pb[j];
        __syncthreads();
#pragma unroll
        for (int kk = 0; kk < 16; ++kk) {
            float4 a4 = *(const float4 *)&As[kk][ty << 2];
            float4 b4a = *(const float4 *)&Bs[kk][tx << 3];
            float4 b4b = *(const float4 *)&Bs[kk][(tx << 3) + 4];
            float av[4] = {a4.x, a4.y, a4.z, a4.w};
            float bv[8] = {b4a.x, b4a.y, b4a.z, b4a.w, b4b.x, b4b.y, b4b.z, b4b.w};
#pragma unroll
            for (int r = 0; r < 4; ++r)
#pragma unroll
                for (int j = 0; j < 8; ++j) acc[r][j] = fmaf(av[r], bv[j], acc[r][j]);
        }
    }
#pragma unroll
    for (int r = 0; r < 4; ++r) {
        int v = m0 + (ty << 2) + r;
        if (v < VOCAB) {
            int colb = n0 + (tx << 3);
            int u = colb >> 2;
            float *dst = g_proj + (size_t)v * NCOL + colb;
            dst[0] = acc[r][0] + __ldg(&bf1[u]);
            dst[1] = acc[r][1] + __ldg(&bi1[u]);
            dst[2] = acc[r][2] + __ldg(&bc1[u]);
            dst[3] = acc[r][3] + __ldg(&bo1[u]);
            dst[4] = acc[r][4] + __ldg(&bf1[u + 1]);
            dst[5] = acc[r][5] + __ldg(&bi1[u + 1]);
            dst[6] = acc[r][6] + __ldg(&bc1[u + 1]);
            dst[7] = acc[r][7] + __ldg(&bo1[u + 1]);
        }
    }
}

// chunk source within a step (continuous chunk numbering; 24,25 = next step's A chunks 0,1)
__device__ __forceinline__ const __half *chunk_src(int c, const __half *hcur, const __half *hnxt) {
    if (c < 8)  return hcur + 256 + c * 32;      // phase A: h1_old
    if (c < 16) return hcur + (c - 8) * 32;      // phase B half1: h2_old
    return hnxt + 256 + ((c - 16) & 7) * 32;     // phase B half2 / next A: h1_new
}

// 16 MMAs on one BK=32 chunk; A and B fragments both via ldmatrix
__device__ __forceinline__ void chunk_body(
    const uint32_t (&a_base)[2], uint32_t abuf, const uint32_t (&wbq)[2],
    uint32_t koff, float (&acc)[2][4][4])
{
#pragma unroll
    for (int ks = 0; ks < 2; ++ks) {
        uint32_t a0[4], a1[4];
        ldmatrix4(a0, a_base[0] + abuf + ks * 32);
        ldmatrix4(a1, a_base[1] + abuf + ks * 32);
        uint32_t b0[4], b1[4];
        ldmatrix4(b0, wbq[0] + koff + ks * 32);    // fn0: {b0[0],b0[1]}, fn1: {b0[2],b0[3]}
        ldmatrix4(b1, wbq[1] + koff + ks * 32);    // fn2, fn3
        mma_f16(acc[0][0], a0, b0 + 0);
        mma_f16(acc[1][0], a1, b0 + 0);
        mma_f16(acc[0][1], a0, b0 + 2);
        mma_f16(acc[1][1], a1, b0 + 2);
        mma_f16(acc[0][2], a0, b1 + 0);
        mma_f16(acc[1][2], a1, b1 + 0);
        mma_f16(acc[0][3], a0, b1 + 2);
        mma_f16(acc[1][3], a1, b1 + 2);
    }
}

// epilogue: combine gate quads via shfl, update c-state, write h (fp16)
template <bool PHASEA>
__device__ __forceinline__ void epilogue(
    float (&acc)[2][4][4], float (&cst)[2][4], const float4 (&ad)[2][4],
    const int (&brow)[2], int ug0, int l, int nxt, bool storef)
{
    const int odd = l & 1;
#pragma unroll
    for (int fm = 0; fm < 2; ++fm) {
        int b = brow[fm];
#pragma unroll
        for (int fn = 0; fn < 4; ++fn) {
            float c0 = acc[fm][fn][0], c1 = acc[fm][fn][1];
            float c2 = acc[fm][fn][2], c3 = acc[fm][fn][3];
            float s0 = __shfl_xor_sync(0xffffffffu, c0, 1);
            float s1 = __shfl_xor_sync(0xffffffffu, c1, 1);
            float s2 = __shfl_xor_sync(0xffffffffu, c2, 1);
            float s3 = __shfl_xor_sync(0xffffffffu, c3, 1);
            float gf = odd ? s2 : c0;
            float gi = odd ? s3 : c1;
            float gc = odd ? c2 : s0;
            float go = odd ? c3 : s1;
            float4 a4 = ad[fm][fn];
            float pf = gf + a4.x, pi = gi + a4.y, pc = gc + a4.z, po = go + a4.w;
            float cn = sigap(pf) * cst[fm][fn] + sigap(pi) * tanhap(pc);
            cst[fm][fn] = cn;
            float h = sigap(po) * tanhap(cn);
            int ug = ug0 + fn * 2;
            int col = (PHASEA ? 256 : 0) + ug;
            g_hbf[nxt][b][col] = __float2half(h);
            if (!PHASEA && storef) g_h2f[b][ug] = h;
        }
    }
}

// ---------------- persistent recurrent kernel ----------------
__global__ __launch_bounds__(256, 1) void lstm_kernel(
    const int *__restrict__ tokens,
    const float *__restrict__ w_out,
    const float *__restrict__ b_out,
    float *__restrict__ out)
{
    extern __shared__ char smem[];
    const uint32_t sb = smem_u32(smem);
    const int tid = threadIdx.x;
    const int bid = blockIdx.x;
    const int wid = tid >> 5, l = tid & 31;
    const int mT = bid >> 4, nT = bid & 15;
    const int m0 = mT << 7;
    const int mw = wid & 3, nw = wid >> 2;
    const int barid = 1 + mw;

    // preload resident fp16 weight slice (100352 B)
    {
        const float4 *src = (const float4 *)(g_Wpk + (size_t)nT * WSLICE);
        float4 *dst = (float4 *)(smem + SM_W1);
        for (int i = tid; i < 6272; i += 256) dst[i] = src[i];
    }

    // A ldmatrix lane addresses (shared CTA-wide A staging, as in R7)
    uint32_t a_base[2];
#pragma unroll
    for (int fm = 0; fm < 2; ++fm)
        a_base[fm] = sb + SM_A + (mw * 32 + fm * 16 + (l & 15)) * A_PITCH + (l >> 4) * 16;
    // B ldmatrix lane addresses: q covers fn pair {2q, 2q+1}
    uint32_t wb1q[2], wb2q[2];
#pragma unroll
    for (int q = 0; q < 2; ++q) {
        int fn = q * 2 + (l >> 4);
        int n = nw * 32 + fn * 8 + (l & 7);
        uint32_t hi = ((l >> 3) & 1) * 16;
        wb1q[q] = sb + SM_W1 + n * 528 + hi;
        wb2q[q] = sb + SM_W2 + n * 1040 + hi;
    }
    const int cp_row = mw * 32 + nw * 16 + (l >> 1);
    const uint32_t cp_dst0 = sb + SM_A + cp_row * A_PITCH + (l & 1) * 32;
    const int srcoff = (l & 1) * 16;

    // epilogue row/col constants
    const int odd = l & 1;
    const int ul_b = nw * 8 + ((l & 3) >> 1);
    const int ug0 = nT * 16 + ul_b;
    int brow[2];
#pragma unroll
    for (int fm = 0; fm < 2; ++fm)
        brow[fm] = m0 + mw * 32 + fm * 16 + (l >> 2) + (odd ? 8 : 0);

    // layer-2 bias addends: constant across steps
    float4 adB[2][4];
#pragma unroll
    for (int fn = 0; fn < 4; ++fn) {
        float4 v = *(const float4 *)(g_b2p + 4 * (ug0 + fn * 2));
        adB[0][fn] = v;
        adB[1][fn] = v;
    }

    float c1st[2][4], c2st[2][4];
#pragma unroll
    for (int a = 0; a < 2; ++a)
#pragma unroll
        for (int b = 0; b < 4; ++b) { c1st[a][b] = 0.f; c2st[a][b] = 0.f; }

    unsigned target = 0;
    __syncthreads();   // weights resident

    // prologue: stage chunks 0,1 of t=0 (h1_old)
    {
        const __half *h0 = &g_hbf[0][m0 + cp_row][0];
        stage(cp_dst0, h0 + 256 + srcoff);
        stage(cp_dst0 + A_BUF, h0 + 288 + srcoff);
    }

#pragma unroll 1
    for (int t = 0; t < TSTEPS; ++t) {
        const int cur = t & 1, nxt = cur ^ 1;
        const __half *hcur = &g_hbf[cur][m0 + cp_row][0];
        const __half *hnxt = &g_hbf[nxt][m0 + cp_row][0];
        const bool last = (t == TSTEPS - 1);

        // hoist epilogue-A addends (token-dependent proj gathers)
        float4 adA[2][4];
#pragma unroll
        for (int fm = 0; fm < 2; ++fm) {
            int tok = __ldg(&tokens[brow[fm] * TSTEPS + t]);
            const float4 *p = (const float4 *)(g_proj + (size_t)tok * NCOL) + ug0;
#pragma unroll
            for (int fn = 0; fn < 4; ++fn) adA[fm][fn] = __ldg(p + fn * 2);
        }

        // ---- SEG A: layer-1, chunks 0..7 ----
        float acc1[2][4][4];
#pragma unroll
        for (int a = 0; a < 2; ++a)
#pragma unroll
            for (int f = 0; f < 4; ++f)
#pragma unroll
                for (int j = 0; j < 4; ++j) acc1[a][f][j] = 0.f;
#pragma unroll
        for (int k = 0; k < 8; ++k) {
            asm volatile("cp.async.wait_group 1;" ::: "memory");
            asm volatile("bar.sync %0, 64;" :: "r"(barid) : "memory");
            stage(cp_dst0 + ((k + 2) % 3) * A_BUF, chunk_src(k + 2, hcur, hnxt) + srcoff);
            chunk_body(a_base, (k % 3) * A_BUF, wb1q, k * 64, acc1);
        }
        epilogue<true>(acc1, c1st, adA, brow, ug0, l, nxt, false);

        // ---- SEG B1: layer-2 over h2_old, chunks 8..15 ----
        float acc2[2][4][4];
#pragma unroll
        for (int a = 0; a < 2; ++a)
#pragma unroll
            for (int f = 0; f < 4; ++f)
#pragma unroll
                for (int j = 0; j < 4; ++j) acc2[a][f][j] = 0.f;
#pragma unroll
        for (int k = 8; k < 16; ++k) {
            if (k < 15) { asm volatile("cp.async.wait_group 1;" ::: "memory"); }
            else        { asm volatile("cp.async.wait_group 0;" ::: "memory"); }
            asm volatile("bar.sync %0, 64;" :: "r"(barid) : "memory");
            if (k + 2 < 16)
                stage(cp_dst0 + ((k + 2) % 3) * A_BUF, chunk_src(k + 2, hcur, hnxt) + srcoff);
            chunk_body(a_base, (k % 3) * A_BUF, wb2q, (k - 8) * 64, acc2);
        }
        gsync(mT, target);

        // ---- SEG B2: layer-2 over h1_new, chunks 16..23 ----
        stage(cp_dst0 + (16 % 3) * A_BUF, chunk_src(16, hcur, hnxt) + srcoff);
        stage(cp_dst0 + (17 % 3) * A_BUF, chunk_src(17, hcur, hnxt) + srcoff);
#pragma unroll
        for (int k = 16; k < 24; ++k) {
            if (k == 23 && last) { asm volatile("cp.async.wait_group 0;" ::: "memory"); }
            else                 { asm volatile("cp.async.wait_group 1;" ::: "memory"); }
            asm volatile("bar.sync %0, 64;" :: "r"(barid) : "memory");
            if (k + 2 < 24 || !last)
                stage(cp_dst0 + ((k + 2) % 3) * A_BUF, chunk_src(k + 2, hcur, hnxt) + srcoff);
            chunk_body(a_base, (k % 3) * A_BUF, wb2q, (k - 8) * 64, acc2);
        }
        epilogue<false>(acc2, c2st, adB, brow, ug0, l, nxt, last);
        gsync(mT, target);
    }

    // ---- output: out[b] = sigmoid(h2[b] . w_out + b_out) ----
    {
        int w = (bid << 3) + wid;
        float s = 0.0f;
#pragma unroll
        for (int k = l; k < UDIM; k += 32)
            s += g_h2f[w][k] * __ldg(&w_out[k]);
#pragma unroll
        for (int off = 16; off > 0; off >>= 1)
            s += __shfl_down_sync(0xffffffffu, s, off);
        if (l == 0) out[w] = sigap(s + __ldg(&b_out[0]));
    }
}

// ---------------- launch ----------------
extern "C" void kernel_launch(void *const *d_in, const int *in_sizes, int n_in,
                              void *d_out, int out_size)
{
    const int   *tokens = (const int *)d_in[0];
    const float *emb = (const float *)d_in[1];
    const float *wf1 = (const float *)d_in[2];
    const float *bf1 = (const float *)d_in[3];
    const float *wi1 = (const float *)d_in[4];
    const float *bi1 = (const float *)d_in[5];
    const float *wc1 = (const float *)d_in[6];
    const float *bc1 = (const float *)d_in[7];
    const float *wo1 = (const float *)d_in[8];
    const float *bo1 = (const float *)d_in[9];
    const float *wf2 = (const float *)d_in[10];
    const float *bf2 = (const float *)d_in[11];
    const float *wi2 = (const float *)d_in[12];
    const float *bi2 = (const float *)d_in[13];
    const float *wc2 = (const float *)d_in[14];
    const float *bc2 = (const float *)d_in[15];
    const float *wo2 = (const float *)d_in[16];
    const float *bo2 = (const float *)d_in[17];
    const float *w_out = (const float *)d_in[18];
    const float *b_out = (const float *)d_in[19];
    float *out = (float *)d_out;

    cudaFuncSetAttribute(lstm_kernel, cudaFuncAttributeMaxDynamicSharedMemorySize, SMEM_TOTAL);

    init_kernel<<<1024, 256>>>(wf1, wi1, wc1, wo1, wf2, wi2, wc2, wo2, bf2, bi2, bc2, bo2);
    proj_kernel<<<1256, 256>>>(emb, wf1, wi1, wc1, wo1, bf1, bi1, bc1, bo1);
    lstm_kernel<<<NBLK, 256, SMEM_TOTAL>>>(tokens, w_out, b_out, out);
}

// round 15
// speedup vs baseline: 1.6477x; 1.0472x over previous
#include <cuda_runtime.h>
#include <cuda_fp16.h>
#include <cstdint>

#define BATCH  1024
#define TSTEPS 80
#define EDIM   100
#define UDIM   256
#define VOCAB  10000
#define NCOL   1024   // 4 gates * U, packed col = u*4+g (g:0=f,1=i,2=c,3=o)
#define NBLK   128
#define THREADS 512

// ---- smem layout (bytes) ----
#define A_PITCH 80
#define A_BUF   10240          // 128 rows * 80
#define SM_A    0              // 3 buffers = 30720
#define SM_W1   30720          // 64 n * 528
#define SM_W2   64512          // 64 n * 1040
#define SMEM_TOTAL 131072

// packed weight slice per nT (fp16 elems)
#define WSLICE   50176         // 64*264 + 64*520
#define W2BASE_E 16896

// ---------------- device scratch ----------------
__device__ float    g_proj[(size_t)VOCAB * NCOL];  // emb@Wx+b1, fp32, gate-interleaved
__device__ __half   g_Wpk[16 * WSLICE];            // packed fp16 weights per nT
__device__ float    g_b2p[NCOL];
__device__ __half   g_hbf[2][BATCH][512];          // [buf][b][col] 0-255 h2, 256-511 h1
__device__ float    g_h2f[BATCH][UDIM];
__device__ unsigned g_cntg[8 * 32];                // per-mT-group barrier counters (padded)

// ---------------- helpers ----------------
__device__ __forceinline__ uint32_t smem_u32(const void *p) {
    uint32_t a;
    asm("{ .reg .u64 t; cvta.to.shared.u64 t, %1; cvt.u32.u64 %0, t; }" : "=r"(a) : "l"(p));
    return a;
}
__device__ __forceinline__ void mma_f16(float *c, const uint32_t *a, const uint32_t *b) {
    asm volatile(
        "mma.sync.aligned.m16n8k16.row.col.f32.f16.f16.f32 "
        "{%0,%1,%2,%3}, {%4,%5,%6,%7}, {%8,%9}, {%0,%1,%2,%3};"
        : "+f"(c[0]), "+f"(c[1]), "+f"(c[2]), "+f"(c[3])
        : "r"(a[0]), "r"(a[1]), "r"(a[2]), "r"(a[3]), "r"(b[0]), "r"(b[1]));
}
__device__ __forceinline__ void ldmatrix4(uint32_t *r, uint32_t addr) {
    asm volatile("ldmatrix.sync.aligned.m8n8.x4.shared.b16 {%0,%1,%2,%3}, [%4];"
                 : "=r"(r[0]), "=r"(r[1]), "=r"(r[2]), "=r"(r[3]) : "r"(addr));
}
__device__ __forceinline__ void cpa16(uint32_t dst, const void *src) {
    asm volatile("cp.async.cg.shared.global [%0], [%1], 16;" :: "r"(dst), "l"(src) : "memory");
}
// one 16B segment per thread per chunk (512 threads cover 128 rows x 64B)
__device__ __forceinline__ void stage1(uint32_t dst, const __half *s) {
    cpa16(dst, s);
    asm volatile("cp.async.commit_group;" ::: "memory");
}
__device__ __forceinline__ float tanhap(float x) {
    float y; asm("tanh.approx.f32 %0, %1;" : "=f"(y) : "f"(x)); return y;
}
__device__ __forceinline__ float sigap(float x) {
    return fmaf(tanhap(0.5f * x), 0.5f, 0.5f);
}
// per-mT-group barrier (16 CTAs): release-red + acquire-ld spin
__device__ __forceinline__ void gsync(int grp, unsigned &target) {
    __syncthreads();
    if (threadIdx.x == 0) {
        unsigned *ctr = &g_cntg[grp * 32];
        asm volatile("red.release.gpu.global.add.u32 [%0], %1;" :: "l"(ctr), "r"(1u) : "memory");
        target += 16;
        unsigned v;
        do {
            asm volatile("ld.acquire.gpu.global.u32 %0, [%1];" : "=r"(v) : "l"(ctr) : "memory");
        } while (v < target);
    }
    __syncthreads();
}

// ---------------- init: pack fp16 weights, zero state ----------------
__global__ void init_kernel(
    const float *wf1, const float *wi1, const float *wc1, const float *wo1,
    const float *wf2, const float *wi2, const float *wc2, const float *wo2,
    const float *bf2, const float *bi2, const float *bc2, const float *bo2)
{
    long i = (long)blockIdx.x * blockDim.x + threadIdx.x;
    long stride = (long)gridDim.x * blockDim.x;
    for (long j = i; j < 524288L; j += stride) ((uint32_t *)g_hbf)[j] = 0u;
    for (long j = i; j < 256; j += stride) g_cntg[j] = 0u;
    for (long j = i; j < 16L * 64L * 768L; j += stride) {
        int nT = (int)(j / (64 * 768));
        int rem = (int)(j % (64 * 768));
        int n = rem / 768, k = rem % 768;
        int col = nT * 64 + n;
        int u = col >> 2, g = col & 3;
        if (k < 256) {
            const float *w = (g == 0) ? wf1 : (g == 1) ? wi1 : (g == 2) ? wc1 : wo1;
            g_Wpk[(long)nT * WSLICE + n * 264 + k] = __float2half(w[k * UDIM + u]);
        } else {
            int k2 = k - 256;
            const float *w = (g == 0) ? wf2 : (g == 1) ? wi2 : (g == 2) ? wc2 : wo2;
            g_Wpk[(long)nT * WSLICE + W2BASE_E + n * 520 + k2] = __float2half(w[k2 * UDIM + u]);
        }
    }
    for (long j = i; j < NCOL; j += stride) {
        int g = (int)(j & 3), u = (int)(j >> 2);
        const float *b = (g == 0) ? bf2 : (g == 1) ? bi2 : (g == 2) ? bc2 : bo2;
        g_b2p[j] = b[u];
    }
}

// ---------------- proj (fp32): proj[v][u*4+g] = emb[v,:] @ W{g}1[x-rows] + b{g}1 ----------------
__global__ __launch_bounds__(256) void proj_kernel(
    const float *__restrict__ emb,
    const float *__restrict__ wf1, const float *__restrict__ wi1,
    const float *__restrict__ wc1, const float *__restrict__ wo1,
    const float *__restrict__ bf1, const float *__restrict__ bi1,
    const float *__restrict__ bc1, const float *__restrict__ bo1)
{
    __shared__ float As[16][68];
    __shared__ float Bs[16][128];
    const int tid = threadIdx.x;
    const int tx = tid & 15, ty = tid >> 4;
    const int bid = blockIdx.x;
    const int mT = bid >> 3, nT = bid & 7;
    const int m0 = mT << 6, n0 = nT << 7;
    const int la_m = tid >> 2, la_k = (tid & 3) << 2;
    const int lb_k = tid >> 4, lb_n = (tid & 15) << 3;

    float acc[4][8];
#pragma unroll
    for (int r = 0; r < 4; ++r)
#pragma unroll
        for (int j = 0; j < 8; ++j) acc[r][j] = 0.0f;

#pragma unroll 1
    for (int kt = 0; kt < 7; ++kt) {
        const int k0 = kt << 4;
        float4 pa = make_float4(0.f, 0.f, 0.f, 0.f);
        {
            int v = m0 + la_m, k = k0 + la_k;
            if (v < VOCAB && k < EDIM)
                pa = *(const float4 *)(emb + (size_t)v * EDIM + k);
        }
        float pb[8];
        {
            int k = k0 + lb_k;
            bool val = (k < EDIM);
            int wrow = (UDIM + k) * UDIM;
            int uc = (n0 + lb_n) >> 2;
            pb[0] = val ? __ldg(&wf1[wrow + uc]) : 0.f;
            pb[1] = val ? __ldg(&wi1[wrow + uc]) : 0.f;
            pb[2] = val ? __ldg(&wc1[wrow + uc]) : 0.f;
            pb[3] = val ? __ldg(&wo1[wrow + uc]) : 0.f;
            pb[4] = val ? __ldg(&wf1[wrow + uc + 1]) : 0.f;
            pb[5] = val ? __ldg(&wi1[wrow + uc + 1]) : 0.f;
            pb[6] = val ? __ldg(&wc1[wrow + uc + 1]) : 0.f;
            pb[7] = val ? __ldg(&wo1[wrow + uc + 1]) : 0.f;
        }
        __syncthreads();
        As[la_k + 0][la_m] = pa.x;
        As[la_k + 1][la_m] = pa.y;
        As[la_k + 2][la_m] = pa.z;
        As[la_k + 3][la_m] = pa.w;
#pragma unroll
        for (int j = 0; j < 8; ++j) Bs[lb_k][lb_n + j] = pb[j];
        __syncthreads();
#pragma unroll
        for (int kk = 0; kk < 16; ++kk) {
            float4 a4 = *(const float4 *)&As[kk][ty << 2];
            float4 b4a = *(const float4 *)&Bs[kk][tx << 3];
            float4 b4b = *(const float4 *)&Bs[kk][(tx << 3) + 4];
            float av[4] = {a4.x, a4.y, a4.z, a4.w};
            float bv[8] = {b4a.x, b4a.y, b4a.z, b4a.w, b4b.x, b4b.y, b4b.z, b4b.w};
#pragma unroll
            for (int r = 0; r < 4; ++r)
#pragma unroll
                for (int j = 0; j < 8; ++j) acc[r][j] = fmaf(av[r], bv[j], acc[r][j]);
        }
    }
#pragma unroll
    for (int r = 0; r < 4; ++r) {
        int v = m0 + (ty << 2) + r;
        if (v < VOCAB) {
            int colb = n0 + (tx << 3);
            int u = colb >> 2;
            float *dst = g_proj + (size_t)v * NCOL + colb;
            dst[0] = acc[r][0] + __ldg(&bf1[u]);
            dst[1] = acc[r][1] + __ldg(&bi1[u]);
            dst[2] = acc[r][2] + __ldg(&bc1[u]);
            dst[3] = acc[r][3] + __ldg(&bo1[u]);
            dst[4] = acc[r][4] + __ldg(&bf1[u + 1]);
            dst[5] = acc[r][5] + __ldg(&bi1[u + 1]);
            dst[6] = acc[r][6] + __ldg(&bc1[u + 1]);
            dst[7] = acc[r][7] + __ldg(&bo1[u + 1]);
        }
    }
}

// chunk source: column base for chunk c (0..25; 24,25 = next step's A chunks 0,1)
__device__ __forceinline__ const __half *chunk_src(int c, const __half *hcur, const __half *hnxt) {
    if (c < 8)  return hcur + 256 + c * 32;      // A: h1_old
    if (c < 16) return hcur + (c - 8) * 32;      // B1: h2_old
    return hnxt + 256 + ((c - 16) & 7) * 32;     // B2 / next A: h1_new
}

// 8 MMAs on one BK=32 chunk (16-row warp tile); A and B via ldmatrix
__device__ __forceinline__ void chunk_body(
    uint32_t a_base, uint32_t abuf, const uint32_t (&wbq)[2],
    uint32_t koff, float (&acc)[4][4])
{
#pragma unroll
    for (int ks = 0; ks < 2; ++ks) {
        uint32_t a[4];
        ldmatrix4(a, a_base + abuf + ks * 32);
        uint32_t b0[4], b1[4];
        ldmatrix4(b0, wbq[0] + koff + ks * 32);    // fn0: {b0[0],b0[1]}, fn1: {b0[2],b0[3]}
        ldmatrix4(b1, wbq[1] + koff + ks * 32);    // fn2, fn3
        mma_f16(acc[0], a, b0 + 0);
        mma_f16(acc[1], a, b0 + 2);
        mma_f16(acc[2], a, b1 + 0);
        mma_f16(acc[3], a, b1 + 2);
    }
}

// epilogue: combine gate quads via shfl, update c-state, write h (fp16)
template <bool PHASEA>
__device__ __forceinline__ void epilogue(
    float (&acc)[4][4], float (&cst)[4], const float4 (&ad)[4],
    int brow, int ug0, int l, int nxt, bool storef)
{
    const int odd = l & 1;
#pragma unroll
    for (int fn = 0; fn < 4; ++fn) {
        float c0 = acc[fn][0], c1 = acc[fn][1];
        float c2 = acc[fn][2], c3 = acc[fn][3];
        float s0 = __shfl_xor_sync(0xffffffffu, c0, 1);
        float s1 = __shfl_xor_sync(0xffffffffu, c1, 1);
        float s2 = __shfl_xor_sync(0xffffffffu, c2, 1);
        float s3 = __shfl_xor_sync(0xffffffffu, c3, 1);
        float gf = odd ? s2 : c0;
        float gi = odd ? s3 : c1;
        float gc = odd ? c2 : s0;
        float go = odd ? c3 : s1;
        float4 a4 = ad[fn];
        float pf = gf + a4.x, pi = gi + a4.y, pc = gc + a4.z, po = go + a4.w;
        float cn = sigap(pf) * cst[fn] + sigap(pi) * tanhap(pc);
        cst[fn] = cn;
        float h = sigap(po) * tanhap(cn);
        int ug = ug0 + fn * 2;
        int col = (PHASEA ? 256 : 0) + ug;
        g_hbf[nxt][brow][col] = __float2half(h);
        if (!PHASEA && storef) g_h2f[brow][ug] = h;
    }
}

// ---------------- persistent recurrent kernel ----------------
__global__ __launch_bounds__(THREADS, 1) void lstm_kernel(
    const int *__restrict__ tokens,
    const float *__restrict__ w_out,
    const float *__restrict__ b_out,
    float *__restrict__ out)
{
    extern __shared__ char smem[];
    const uint32_t sb = smem_u32(smem);
    const int tid = threadIdx.x;
    const int bid = blockIdx.x;
    const int wid = tid >> 5, l = tid & 31;
    const int mT = bid >> 4, nT = bid & 15;
    const int m0 = mT << 7;
    const int mw = wid & 7, nw = wid >> 3;     // 8 m-stripes of 16 rows, 2 n-halves
    const int barid = 1 + mw;

    // preload resident fp16 weight slice (100352 B)
    {
        const float4 *src = (const float4 *)(g_Wpk + (size_t)nT * WSLICE);
        float4 *dst = (float4 *)(smem + SM_W1);
        for (int i = tid; i < 6272; i += THREADS) dst[i] = src[i];
    }

    // A ldmatrix lane address (16-row stripe)
    const uint32_t a_base = sb + SM_A + (mw * 16 + (l & 15)) * A_PITCH + (l >> 4) * 16;
    // B ldmatrix lane addresses: q covers fn pair {2q, 2q+1}
    uint32_t wb1q[2], wb2q[2];
#pragma unroll
    for (int q = 0; q < 2; ++q) {
        int fn = q * 2 + (l >> 4);
        int n = nw * 32 + fn * 8 + (l & 7);
        uint32_t hi = ((l >> 3) & 1) * 16;
        wb1q[q] = sb + SM_W1 + n * 528 + hi;
        wb2q[q] = sb + SM_W2 + n * 1040 + hi;
    }
    // staging: pair (mw, nw=0/1) covers stripe rows; thread stages one 16B segment
    const int p = nw * 32 + l;               // 0..63 within pair
    const int cp_row = mw * 16 + (p >> 2);
    const int seg = p & 3;
    const uint32_t cp_base = sb + SM_A + cp_row * A_PITCH + seg * 16;
    const int srcoff = seg * 8;              // halves

    // epilogue row/col constants
    const int odd = l & 1;
    const int ul_b = nw * 8 + ((l & 3) >> 1);
    const int ug0 = nT * 16 + ul_b;
    const int brow = m0 + mw * 16 + (l >> 2) + (odd ? 8 : 0);

    // layer-2 bias addends: constant across steps
    float4 adB[4];
#pragma unroll
    for (int fn = 0; fn < 4; ++fn)
        adB[fn] = *(const float4 *)(g_b2p + 4 * (ug0 + fn * 2));

    float c1st[4], c2st[4];
#pragma unroll
    for (int a = 0; a < 4; ++a) { c1st[a] = 0.f; c2st[a] = 0.f; }

    unsigned target = 0;
    __syncthreads();   // weights resident

    // prologue: stage chunks 0,1 of t=0 (h1_old = zeros)
    {
        const __half *h0 = &g_hbf[0][m0 + cp_row][0];
        stage1(cp_base + 0 * A_BUF, h0 + 256 + srcoff);
        stage1(cp_base + 1 * A_BUF, h0 + 288 + srcoff);
    }

#pragma unroll 1
    for (int t = 0; t < TSTEPS; ++t) {
        const int cur = t & 1, nxt = cur ^ 1;
        const __half *hcur = &g_hbf[cur][m0 + cp_row][0];
        const __half *hnxt = &g_hbf[nxt][m0 + cp_row][0];
        const bool last = (t == TSTEPS - 1);

        // hoist epilogue-A addends (token-dependent proj gathers)
        float4 adA[4];
        {
            int tok = __ldg(&tokens[brow * TSTEPS + t]);
            const float4 *pp = (const float4 *)(g_proj + (size_t)tok * NCOL) + ug0;
#pragma unroll
            for (int fn = 0; fn < 4; ++fn) adA[fn] = __ldg(pp + fn * 2);
        }

        // ---- SEG A: layer-1, chunks 0..7 (reads h1_old) ----
        float acc1[4][4];
#pragma unroll
        for (int f = 0; f < 4; ++f)
#pragma unroll
            for (int j = 0; j < 4; ++j) acc1[f][j] = 0.f;
#pragma unroll
        for (int k = 0; k < 8; ++k) {
            if (k < 7) { asm volatile("cp.async.wait_group 1;" ::: "memory"); }
            else       { asm volatile("cp.async.wait_group 0;" ::: "memory"); }
            asm volatile("bar.sync %0, 64;" :: "r"(barid) : "memory");
            if (k < 6)
                stage1(cp_base + ((k + 2) % 3) * A_BUF, chunk_src(k + 2, hcur, hnxt) + srcoff);
            chunk_body(a_base, (k % 3) * A_BUF, wb1q, k * 64, acc1);
        }
        epilogue<true>(acc1, c1st, adA, brow, ug0, l, nxt, false);

        gsync(mT, target);   // h1_new visible group-wide; h2_old (epiB of t-1) transitively too

        // ---- SEG B: layer-2, order B2 (h1_new, chunks 16..23) then B1 (h2_old, 8..15) ----
        float acc2[4][4];
#pragma unroll
        for (int f = 0; f < 4; ++f)
#pragma unroll
            for (int j = 0; j < 4; ++j) acc2[f][j] = 0.f;
        // restart pipeline: stage first two B chunks (bufs (8+0)%3=2, (8+1)%3=0)
        stage1(cp_base + 2 * A_BUF, chunk_src(16, hcur, hnxt) + srcoff);
        stage1(cp_base + 0 * A_BUF, chunk_src(17, hcur, hnxt) + srcoff);
#pragma unroll
        for (int j = 0; j < 16; ++j) {
            const int c = (j < 8) ? (16 + j) : j;   // 16..23 then 8..15
            if (j == 15 && last) { asm volatile("cp.async.wait_group 0;" ::: "memory"); }
            else                 { asm volatile("cp.async.wait_group 1;" ::: "memory"); }
            asm volatile("bar.sync %0, 64;" :: "r"(barid) : "memory");
            if (j < 14) {
                const int c2 = (j + 2 < 8) ? (16 + j + 2) : (j + 2);
                stage1(cp_base + ((8 + j + 2) % 3) * A_BUF, chunk_src(c2, hcur, hnxt) + srcoff);
            } else if (!last) {
                // stage next step's A chunks 0,1 (h1_new buffer)
                stage1(cp_base + ((8 + j + 2) % 3) * A_BUF,
                       chunk_src(24 + (j - 14), hcur, hnxt) + srcoff);
            }
            chunk_body(a_base, ((8 + j) % 3) * A_BUF, wb2q, (c - 8) * 64, acc2);
        }
        epilogue<false>(acc2, c2st, adB, brow, ug0, l, nxt, last);
    }

    // final barrier: all 16 CTAs of the group must finish epiB(T-1) before
    // any CTA reads g_h2f rows written by its peers (this was the R10 bug).
    gsync(mT, target);

    // ---- output: out[b] = sigmoid(h2[b] . w_out + b_out) ----
    if (wid < 8) {
        int w = (bid << 3) + wid;
        float s = 0.0f;
#pragma unroll
        for (int k = l; k < UDIM; k += 32)
            s += g_h2f[w][k] * __ldg(&w_out[k]);
#pragma unroll
        for (int off = 16; off > 0; off >>= 1)
            s += __shfl_down_sync(0xffffffffu, s, off);
        if (l == 0) out[w] = sigap(s + __ldg(&b_out[0]));
    }
}

// ---------------- launch ----------------
extern "C" void kernel_launch(void *const *d_in, const int *in_sizes, int n_in,
                              void *d_out, int out_size)
{
    const int   *tokens = (const int *)d_in[0];
    const float *emb = (const float *)d_in[1];
    const float *wf1 = (const float *)d_in[2];
    const float *bf1 = (const float *)d_in[3];
    const float *wi1 = (const float *)d_in[4];
    const float *bi1 = (const float *)d_in[5];
    const float *wc1 = (const float *)d_in[6];
    const float *bc1 = (const float *)d_in[7];
    const float *wo1 = (const float *)d_in[8];
    const float *bo1 = (const float *)d_in[9];
    const float *wf2 = (const float *)d_in[10];
    const float *bf2 = (const float *)d_in[11];
    const float *wi2 = (const float *)d_in[12];
    const float *bi2 = (const float *)d_in[13];
    const float *wc2 = (const float *)d_in[14];
    const float *bc2 = (const float *)d_in[15];
    const float *wo2 = (const float *)d_in[16];
    const float *bo2 = (const float *)d_in[17];
    const float *w_out = (const float *)d_in[18];
    const float *b_out = (const float *)d_in[19];
    float *out = (float *)d_out;

    cudaFuncSetAttribute(lstm_kernel, cudaFuncAttributeMaxDynamicSharedMemorySize, SMEM_TOTAL);

    init_kernel<<<1024, 256>>>(wf1, wi1, wc1, wo1, wf2, wi2, wc2, wo2, bf2, bi2, bc2, bo2);
    proj_kernel<<<1256, 256>>>(emb, wf1, wi1, wc1, wo1, bf1, bi1, bc1, bo1);
    lstm_kernel<<<NBLK, THREADS, SMEM_TOTAL>>>(tokens, w_out, b_out, out);
}